// round 12
// baseline (speedup 1.0000x reference)
#include <cuda_runtime.h>
#include <stdint.h>

#define D   128
#define NT  256

// SMEM float offsets (all tiles XOR-swizzled, no padding)
#define XS  0                    // x tile  [64][128] tf32-rounded  (32KB)
#define HS  8192                 // h tile  [64][128] tf32-rounded; later r*h
#define WP  16384                // weight half-panel [128n][64k]   (32KB)
#define SB  24576                // 384 bias floats
#define SMEM_BYTES ((SB + 384) * 4)   // 99,840 B -> 2 CTAs/SM

// ---------------------------------------------------------------------------
// bias precompute: column sums of the three 128x128 "bias" matrices
// ---------------------------------------------------------------------------
__device__ float g_bias[3 * D];

__global__ void bias_kernel(const float* __restrict__ Bz,
                            const float* __restrict__ Br,
                            const float* __restrict__ Bh) {
    int j = threadIdx.x;
    float sz = 0.f, sr = 0.f, sh = 0.f;
    for (int i = 0; i < D; ++i) {
        sz += Bz[i * D + j];
        sr += Br[i * D + j];
        sh += Bh[i * D + j];
    }
    g_bias[j] = sz; g_bias[D + j] = sr; g_bias[2 * D + j] = sh;
}

// ---------------------------------------------------------------------------
// helpers
// ---------------------------------------------------------------------------
__device__ __forceinline__ float f2tf(float f) {          // round fp32 -> tf32 grid
    uint32_t u;
    asm("cvt.rna.tf32.f32 %0, %1;" : "=r"(u) : "f"(f));
    return __uint_as_float(u);
}
__device__ __forceinline__ float sigmoidf_(float v) { return 1.0f / (1.0f + expf(-v)); }

__device__ __forceinline__ void mma8(float* d, const uint32_t* a, uint32_t b0, uint32_t b1) {
    asm volatile(
        "mma.sync.aligned.m16n8k8.row.col.f32.tf32.tf32.f32 "
        "{%0,%1,%2,%3}, {%4,%5,%6,%7}, {%8,%9}, {%0,%1,%2,%3};"
        : "+f"(d[0]), "+f"(d[1]), "+f"(d[2]), "+f"(d[3])
        : "r"(a[0]), "r"(a[1]), "r"(a[2]), "r"(a[3]), "r"(b0), "r"(b1));
}

// ---------------------------------------------------------------------------
// weight half-panel prefetch (gmem->regs) and swizzled store (regs->SMEM [n][k])
// panel element (n, k) stored at n*64 + (k ^ ((n&7)<<2))
// tr  mapping: thread owns (n = lin&127, kq = lin>>7)  -> coalesced gmem columns
// nat mapping: thread owns (kq = lin&15, n  = lin>>4)  -> coalesced gmem rows
// ---------------------------------------------------------------------------
__device__ __forceinline__ void ldg_tr(const float* __restrict__ w, int half,
                                       float4* pf, int tid) {
#pragma unroll
    for (int i = 0; i < 8; ++i) {
        int lin = tid + i * NT;
        int n = lin & 127, kq = lin >> 7;
        int gk = half * 64 + kq * 4;
        pf[i] = make_float4(f2tf(w[(gk + 0) * D + n]), f2tf(w[(gk + 1) * D + n]),
                            f2tf(w[(gk + 2) * D + n]), f2tf(w[(gk + 3) * D + n]));
    }
}
__device__ __forceinline__ void ldg_trsum(const float* __restrict__ wa,
                                          const float* __restrict__ wb, int half,
                                          float4* pf, int tid) {
#pragma unroll
    for (int i = 0; i < 8; ++i) {
        int lin = tid + i * NT;
        int n = lin & 127, kq = lin >> 7;
        int gk = half * 64 + kq * 4;
        pf[i] = make_float4(f2tf(wa[(gk + 0) * D + n] + wb[(gk + 0) * D + n]),
                            f2tf(wa[(gk + 1) * D + n] + wb[(gk + 1) * D + n]),
                            f2tf(wa[(gk + 2) * D + n] + wb[(gk + 2) * D + n]),
                            f2tf(wa[(gk + 3) * D + n] + wb[(gk + 3) * D + n]));
    }
}
__device__ __forceinline__ void ldg_nat(const float* __restrict__ w, int half,
                                        float4* pf, int tid) {
#pragma unroll
    for (int i = 0; i < 8; ++i) {
        int lin = tid + i * NT;
        int kq = lin & 15, n = lin >> 4;
        float4 v = *(const float4*)(w + n * D + half * 64 + kq * 4);
        pf[i] = make_float4(f2tf(v.x), f2tf(v.y), f2tf(v.z), f2tf(v.w));
    }
}
__device__ __forceinline__ void sts_tr(float* __restrict__ buf, const float4* pf, int tid) {
#pragma unroll
    for (int i = 0; i < 8; ++i) {
        int lin = tid + i * NT;
        int n = lin & 127, kq = lin >> 7;
        *(float4*)(buf + n * 64 + ((kq * 4) ^ ((n & 7) << 2))) = pf[i];
    }
}
__device__ __forceinline__ void sts_nat(float* __restrict__ buf, const float4* pf, int tid) {
#pragma unroll
    for (int i = 0; i < 8; ++i) {
        int lin = tid + i * NT;
        int kq = lin & 15, n = lin >> 4;
        *(float4*)(buf + n * 64 + ((kq * 4) ^ ((n & 7) << 2))) = pf[i];
    }
}

// ---------------------------------------------------------------------------
// one K-half GEMM slab: 32M x 32N x 64K per warp (2 msub x 4 nsub mma tiles)
// A tile 128-wide swizzled; koff = 0 or 64 selects K-half. Panel is [n][64].
// A row & B row both have (row&7)==g, so one swizzled offset pair serves both.
// ---------------------------------------------------------------------------
__device__ __forceinline__ void mma_slab(const float* __restrict__ As, int koff,
                                         const float* __restrict__ Ws,
                                         float acc[8][4],
                                         int mrow0, int ncol0, int g, int t) {
    const float* a0 = As + (mrow0 + g) * D + koff;   // msub0 rows g, g+8
    const float* a1 = a0 + 8 * D;
    const float* a2 = a0 + 16 * D;                   // msub1 rows g+16, g+24
    const float* a3 = a0 + 24 * D;
#pragma unroll
    for (int kk = 0; kk < 8; ++kk) {
        const int off1 = (kk * 8 + t) ^ (g << 2);
        const int off2 = off1 ^ 4;
        uint32_t A0[4], A1[4];
        A0[0] = __float_as_uint(a0[off1]); A0[1] = __float_as_uint(a1[off1]);
        A0[2] = __float_as_uint(a0[off2]); A0[3] = __float_as_uint(a1[off2]);
        A1[0] = __float_as_uint(a2[off1]); A1[1] = __float_as_uint(a3[off1]);
        A1[2] = __float_as_uint(a2[off2]); A1[3] = __float_as_uint(a3[off2]);
#pragma unroll
        for (int ns = 0; ns < 4; ++ns) {
            const float* bp = Ws + (ncol0 + ns * 8 + g) * 64;
            uint32_t b0 = __float_as_uint(bp[off1]);
            uint32_t b1 = __float_as_uint(bp[off2]);
            mma8(acc[ns],     A0, b0, b1);
            mma8(acc[4 + ns], A1, b0, b1);
        }
    }
}

#define ZERO_ACC(A)                                      \
    _Pragma("unroll") for (int q = 0; q < 8; ++q)        \
    _Pragma("unroll") for (int j = 0; j < 4; ++j) (A)[q][j] = 0.f

// ---------------------------------------------------------------------------
// fused GRU: one CTA = 64 rows, 256 threads, 2 CTAs/SM, 10 half-GEMM slabs
// ---------------------------------------------------------------------------
__global__ __launch_bounds__(NT, 2)
void gru_kernel(const float* __restrict__ x, const float* __restrict__ h,
                const float* __restrict__ Wz, const float* __restrict__ Uz,
                const float* __restrict__ Wr, const float* __restrict__ Ur,
                const float* __restrict__ Wh, const float* __restrict__ Uh,
                float* __restrict__ out, long long half_off) {
    extern __shared__ float sm[];
    const int tid   = threadIdx.x;
    const int lane  = tid & 31;
    const int warp  = tid >> 5;
    const int g     = lane >> 2;
    const int t     = lane & 3;
    const int mrow0 = (warp >> 2) * 32;     // 0 or 32
    const int ncol0 = (warp & 3) * 32;      // 0,32,64,96
    const long long row0 = (long long)blockIdx.x * 64;

    // ---- stage x, h (both tf32-rounded) into swizzled tiles ----
#pragma unroll
    for (int i = 0; i < 8; ++i) {
        int idx = tid + i * NT;
        int r = idx >> 5, c = (idx & 31) << 2;
        int sw = r * D + (c ^ ((r & 7) << 2));
        float4 vx = *(const float4*)(x + (row0 + r) * D + c);
        *(float4*)(sm + XS + sw) = make_float4(f2tf(vx.x), f2tf(vx.y), f2tf(vx.z), f2tf(vx.w));
        float4 vh = *(const float4*)(h + (row0 + r) * D + c);
        *(float4*)(sm + HS + sw) = make_float4(f2tf(vh.x), f2tf(vh.y), f2tf(vh.z), f2tf(vh.w));
    }
    for (int i = tid; i < 384; i += NT) sm[SB + i] = g_bias[i];

    float4 pf[8];
    ldg_tr(Wz, 0, pf, tid); sts_tr(sm + WP, pf, tid);
    __syncthreads();

    float accZ[8][4], acc[8][4];
    ZERO_ACC(accZ);

    // S0: accZ += x(k0:63) @ Wz(h0)
    ldg_tr(Wz, 1, pf, tid);
    mma_slab(sm + XS, 0, sm + WP, accZ, mrow0, ncol0, g, t);
    __syncthreads(); sts_tr(sm + WP, pf, tid); __syncthreads();
    // S1: x(k64:127) @ Wz(h1)
    ldg_tr(Uz, 0, pf, tid);
    mma_slab(sm + XS, 64, sm + WP, accZ, mrow0, ncol0, g, t);
    __syncthreads(); sts_tr(sm + WP, pf, tid); __syncthreads();
    // S2: h @ Uz(h0)
    ldg_tr(Uz, 1, pf, tid);
    mma_slab(sm + HS, 0, sm + WP, accZ, mrow0, ncol0, g, t);
    __syncthreads(); sts_tr(sm + WP, pf, tid); __syncthreads();
    // S3: h @ Uz(h1)
    ldg_trsum(Wr, Ur, 0, pf, tid);
    mma_slab(sm + HS, 64, sm + WP, accZ, mrow0, ncol0, g, t);
    __syncthreads(); sts_tr(sm + WP, pf, tid); __syncthreads();
    // S4: acc = x @ (Wr+Ur)(h0)
    ldg_trsum(Wr, Ur, 1, pf, tid);
    ZERO_ACC(acc);
    mma_slab(sm + XS, 0, sm + WP, acc, mrow0, ncol0, g, t);
    __syncthreads(); sts_tr(sm + WP, pf, tid); __syncthreads();
    // S5: x @ (Wr+Ur)(h1)
    ldg_nat(Wh, 0, pf, tid);
    mma_slab(sm + XS, 64, sm + WP, acc, mrow0, ncol0, g, t);

    // ---- E1: z = sigmoid(accZ+bz) in place; HS <- f2tf(sigmoid(acc+br) * h) ----
#pragma unroll
    for (int a8 = 0; a8 < 8; ++a8) {
        int ns = a8 & 3, ms = a8 >> 2;
        int c0 = ncol0 + ns * 8 + 2 * t;
        float bz0 = sm[SB + c0], bz1 = sm[SB + c0 + 1];
        accZ[a8][0] = sigmoidf_(accZ[a8][0] + bz0);
        accZ[a8][1] = sigmoidf_(accZ[a8][1] + bz1);
        accZ[a8][2] = sigmoidf_(accZ[a8][2] + bz0);
        accZ[a8][3] = sigmoidf_(accZ[a8][3] + bz1);

        float br0 = sm[SB + D + c0], br1 = sm[SB + D + c0 + 1];
        int r1 = mrow0 + ms * 16 + g;
        int swc = c0 ^ (g << 2);
        float2 hA = *(float2*)(sm + HS + r1 * D + swc);
        float2 hB = *(float2*)(sm + HS + (r1 + 8) * D + swc);
        float q0 = sigmoidf_(acc[a8][0] + br0);
        float q1 = sigmoidf_(acc[a8][1] + br1);
        float q2 = sigmoidf_(acc[a8][2] + br0);
        float q3 = sigmoidf_(acc[a8][3] + br1);
        *(float2*)(sm + HS + r1 * D + swc)       = make_float2(f2tf(q0 * hA.x), f2tf(q1 * hA.y));
        *(float2*)(sm + HS + (r1 + 8) * D + swc) = make_float2(f2tf(q2 * hB.x), f2tf(q3 * hB.y));
    }
    __syncthreads(); sts_nat(sm + WP, pf, tid); __syncthreads();

    // S6: acc = x @ Wh^T(h0)
    ldg_nat(Wh, 1, pf, tid);
    ZERO_ACC(acc);
    mma_slab(sm + XS, 0, sm + WP, acc, mrow0, ncol0, g, t);
    __syncthreads(); sts_nat(sm + WP, pf, tid); __syncthreads();
    // S7: x @ Wh^T(h1)
    ldg_nat(Uh, 0, pf, tid);
    mma_slab(sm + XS, 64, sm + WP, acc, mrow0, ncol0, g, t);
    __syncthreads(); sts_nat(sm + WP, pf, tid); __syncthreads();
    // S8: rh @ Uh^T(h0)   (HS now holds rounded r*h)
    ldg_nat(Uh, 1, pf, tid);
    mma_slab(sm + HS, 0, sm + WP, acc, mrow0, ncol0, g, t);
    __syncthreads(); sts_nat(sm + WP, pf, tid); __syncthreads();
    // S9: rh @ Uh^T(h1)
    mma_slab(sm + HS, 64, sm + WP, acc, mrow0, ncol0, g, t);

    // ---- E2: h_cand = tanh(acc+bh); h_t = (1-z)*h_exact + z*h_cand ----
#pragma unroll
    for (int a8 = 0; a8 < 8; ++a8) {
        int ns = a8 & 3, ms = a8 >> 2;
        int c0 = ncol0 + ns * 8 + 2 * t;
        float bh0 = sm[SB + 2 * D + c0], bh1 = sm[SB + 2 * D + c0 + 1];
        long long gr1 = row0 + mrow0 + ms * 16 + g, gr2 = gr1 + 8;
        float2 hA = *(const float2*)(h + gr1 * D + c0);   // exact h from gmem
        float2 hB = *(const float2*)(h + gr2 * D + c0);
        float hc0 = tanhf(acc[a8][0] + bh0);
        float hc1 = tanhf(acc[a8][1] + bh1);
        float hc2 = tanhf(acc[a8][2] + bh0);
        float hc3 = tanhf(acc[a8][3] + bh1);
        float ht0 = (1.f - accZ[a8][0]) * hA.x + accZ[a8][0] * hc0;
        float ht1 = (1.f - accZ[a8][1]) * hA.y + accZ[a8][1] * hc1;
        float ht2 = (1.f - accZ[a8][2]) * hB.x + accZ[a8][2] * hc2;
        float ht3 = (1.f - accZ[a8][3]) * hB.y + accZ[a8][3] * hc3;
        *(float2*)(out + gr1 * D + c0)            = make_float2(ht0, ht1);
        *(float2*)(out + gr2 * D + c0)            = make_float2(ht2, ht3);
        *(float2*)(out + half_off + gr1 * D + c0) = make_float2(hc0, hc1);
        *(float2*)(out + half_off + gr2 * D + c0) = make_float2(hc2, hc3);
    }
}

// ---------------------------------------------------------------------------
// launch
// ---------------------------------------------------------------------------
extern "C" void kernel_launch(void* const* d_in, const int* in_sizes, int n_in,
                              void* d_out, int out_size) {
    const float* x  = (const float*)d_in[0];
    const float* h  = (const float*)d_in[1];
    const float* Wz = (const float*)d_in[2];
    const float* Uz = (const float*)d_in[3];
    const float* Bz = (const float*)d_in[4];
    const float* Wr = (const float*)d_in[5];
    const float* Ur = (const float*)d_in[6];
    const float* Br = (const float*)d_in[7];
    const float* Wh = (const float*)d_in[8];
    const float* Uh = (const float*)d_in[9];
    const float* Bh = (const float*)d_in[10];

    const int rows = in_sizes[0] / D;      // 262144
    const int grid = rows / 64;            // 4096

    cudaFuncSetAttribute(gru_kernel, cudaFuncAttributeMaxDynamicSharedMemorySize, SMEM_BYTES);

    bias_kernel<<<1, D>>>(Bz, Br, Bh);

    long long half_off = (long long)out_size / 2;   // h_t first, h_cand second
    gru_kernel<<<grid, NT, SMEM_BYTES>>>(x, h, Wz, Uz, Wr, Ur, Wh, Uh,
                                         (float*)d_out, half_off);
}

// round 13
// speedup vs baseline: 1.1325x; 1.1325x over previous
#include <cuda_runtime.h>
#include <stdint.h>

#define D  128
#define NT 512

// SMEM float offsets
#define XS 0            // x tile [64][128] tf32-rounded, swizzled (32KB)
#define HS 8192         // h tile [64][128] tf32-rounded; later r*h  (32KB)
#define P0 16384        // quarter-panel buffer 0 (16KB)
#define P1 20480        // quarter-panel buffer 1 (16KB)
#define SMEM_BYTES (24576 * 4)   // 96KB -> 2 CTAs/SM

// ---------------------------------------------------------------------------
// device globals: biases + prepped weight panel images
// ---------------------------------------------------------------------------
__device__ float g_bias[3 * D];
__device__ float g_wp[20 * 4096];   // 20 quarter-panels (Wz,Uz,Wr+Ur,Wh,Uh) x 4

__global__ void bias_kernel(const float* __restrict__ Bz,
                            const float* __restrict__ Br,
                            const float* __restrict__ Bh) {
    int j = threadIdx.x;
    float sz = 0.f, sr = 0.f, sh = 0.f;
    for (int i = 0; i < D; ++i) {
        sz += Bz[i * D + j];
        sr += Br[i * D + j];
        sh += Bh[i * D + j];
    }
    g_bias[j] = sz; g_bias[D + j] = sr; g_bias[2 * D + j] = sh;
}

__device__ __forceinline__ float f2tf(float f) {      // round fp32 -> tf32 grid
    uint32_t u;
    asm("cvt.rna.tf32.f32 %0, %1;" : "=r"(u) : "f"(f));
    return __uint_as_float(u);
}
__device__ __forceinline__ float sigmoidf_(float v) { return 1.0f / (1.0f + expf(-v)); }

// Bake weights into SMEM-image layout: panel p = G*4 + q (G: Wz,Uz,Wr+Ur,Wh,Uh).
// Element B_G(n,k), k = q*32+k', stored at p*4096 + n*32 + (k' ^ ((n&7)<<2)).
// G0..2 transposed (B = W^T -> computes x@W); G3..4 natural (B = W -> x@W^T).
__global__ void prep_kernel(const float* __restrict__ Wz, const float* __restrict__ Uz,
                            const float* __restrict__ Wr, const float* __restrict__ Ur,
                            const float* __restrict__ Wh, const float* __restrict__ Uh) {
    int idx = blockIdx.x * blockDim.x + threadIdx.x;   // 81920 total
    int G   = idx >> 14;
    int rem = idx & 16383;
    int q   = rem >> 12;
    int r2  = rem & 4095;
    int n   = r2 >> 5;
    int kx  = r2 & 31;
    int k   = q * 32 + (kx ^ ((n & 7) << 2));
    float v;
    if      (G == 0) v = Wz[k * D + n];
    else if (G == 1) v = Uz[k * D + n];
    else if (G == 2) v = Wr[k * D + n] + Ur[k * D + n];
    else if (G == 3) v = Wh[n * D + k];
    else             v = Uh[n * D + k];
    g_wp[idx] = f2tf(v);
}

// ---------------------------------------------------------------------------
// mma helpers
// ---------------------------------------------------------------------------
__device__ __forceinline__ void mma8(float* d, const uint32_t* a, uint32_t b0, uint32_t b1) {
    asm volatile(
        "mma.sync.aligned.m16n8k8.row.col.f32.tf32.tf32.f32 "
        "{%0,%1,%2,%3}, {%4,%5,%6,%7}, {%8,%9}, {%0,%1,%2,%3};"
        : "+f"(d[0]), "+f"(d[1]), "+f"(d[2]), "+f"(d[3])
        : "r"(a[0]), "r"(a[1]), "r"(a[2]), "r"(a[3]), "r"(b0), "r"(b1));
}

// one quarter-K slab: warp tile 16M x 32N x 32K
// A tile: [64][128] swizzled (col c at c ^ ((r&7)<<2)); panel: [128n][32k] swizzled.
// For both, row&7 == g, so the swizzled k-offsets off1/off2 are shared.
__device__ __forceinline__ void mma_q(const float* __restrict__ As, int koff,
                                      const float* __restrict__ Ws,
                                      float acc[4][4],
                                      int mrow0, int ncol0, int g, int t) {
    const float* a0 = As + (mrow0 + g) * D + koff;
    const float* a1 = a0 + 8 * D;
#pragma unroll
    for (int kk = 0; kk < 4; ++kk) {
        const int off1 = (kk * 8 + t) ^ (g << 2);
        const int off2 = off1 ^ 4;
        uint32_t A[4];
        A[0] = __float_as_uint(a0[off1]);
        A[1] = __float_as_uint(a1[off1]);
        A[2] = __float_as_uint(a0[off2]);
        A[3] = __float_as_uint(a1[off2]);
#pragma unroll
        for (int ns = 0; ns < 4; ++ns) {
            const float* bp = Ws + (ncol0 + ns * 8 + g) * 32;
            mma8(acc[ns], A, __float_as_uint(bp[off1]), __float_as_uint(bp[off2]));
        }
    }
}

// ---------------------------------------------------------------------------
// fused GRU: 64 rows/CTA, 512 threads (16 warps of 16x32), 2 CTAs/SM
// 20 quarter-slabs, double-buffered panels, 1 sync per slab
// ---------------------------------------------------------------------------
__global__ __launch_bounds__(NT, 2)
void gru_kernel(const float* __restrict__ x, const float* __restrict__ h,
                float* __restrict__ out, long long half_off) {
    extern __shared__ float sm[];
    const int tid   = threadIdx.x;
    const int lane  = tid & 31;
    const int warp  = tid >> 5;
    const int g     = lane >> 2;
    const int t     = lane & 3;
    const int mrow0 = (warp >> 2) * 16;    // 0,16,32,48
    const int ncol0 = (warp & 3) * 32;     // 0,32,64,96
    const long long row0 = (long long)blockIdx.x * 64;

    // ---- stage x, h (tf32-rounded) into swizzled tiles ----
#pragma unroll
    for (int i = 0; i < 4; ++i) {
        int idx = tid + i * NT;
        int r = idx >> 5, c = (idx & 31) << 2;
        int sw = r * D + (c ^ ((r & 7) << 2));
        float4 vx = *(const float4*)(x + (row0 + r) * D + c);
        *(float4*)(sm + XS + sw) = make_float4(f2tf(vx.x), f2tf(vx.y), f2tf(vx.z), f2tf(vx.w));
        float4 vh = *(const float4*)(h + (row0 + r) * D + c);
        *(float4*)(sm + HS + sw) = make_float4(f2tf(vh.x), f2tf(vh.y), f2tf(vh.z), f2tf(vh.w));
    }

    // ---- panel pipeline prologue: img0 -> P0; preload img1 ----
    float4 pf0, pf1;
    {
        const float4* sp = (const float4*)(g_wp);
        pf0 = sp[tid]; pf1 = sp[tid + NT];
        float4* db = (float4*)(sm + P0);
        db[tid] = pf0; db[tid + NT] = pf1;
        sp = (const float4*)(g_wp + 4096);
        pf0 = sp[tid]; pf1 = sp[tid + NT];
    }
    __syncthreads();

    float accZ[4][4], accR[4][4];
#pragma unroll
    for (int ns = 0; ns < 4; ++ns)
#pragma unroll
        for (int j = 0; j < 4; ++j) { accZ[ns][j] = 0.f; accR[ns][j] = 0.f; }

    // iter p: STS buf[(p+1)&1] <- pf(img p+1); LDG pf <- img p+2; mma buf[p&1]; sync
#define QITER(p, ABASE, ACC) do {                                            \
        if ((p) < 19) {                                                      \
            float4* db = (float4*)(sm + ((((p) + 1) & 1) ? P1 : P0));        \
            db[tid] = pf0; db[tid + NT] = pf1;                               \
        }                                                                    \
        if ((p) < 18) {                                                      \
            const float4* sp = (const float4*)(g_wp + ((p) + 2) * 4096);     \
            pf0 = sp[tid]; pf1 = sp[tid + NT];                               \
        }                                                                    \
        mma_q(sm + (ABASE), ((p) & 3) * 32, sm + (((p) & 1) ? P1 : P0),      \
              ACC, mrow0, ncol0, g, t);                                      \
        __syncthreads();                                                     \
    } while (0)

    // z_pre = x@Wz + h@Uz
    QITER(0, XS, accZ);  QITER(1, XS, accZ);  QITER(2, XS, accZ);  QITER(3, XS, accZ);
    QITER(4, HS, accZ);  QITER(5, HS, accZ);  QITER(6, HS, accZ);  QITER(7, HS, accZ);
    // r_pre = x@(Wr+Ur)
    QITER(8, XS, accR);  QITER(9, XS, accR);  QITER(10, XS, accR); QITER(11, XS, accR);

    // ---- E1: z = sigmoid(z_pre+bz) in accZ; HS <- f2tf(sigmoid(r_pre+br) * h); accR -> 0
#pragma unroll
    for (int ns = 0; ns < 4; ++ns) {
        int c0 = ncol0 + ns * 8 + 2 * t;
        float bz0 = __ldg(&g_bias[c0]), bz1 = __ldg(&g_bias[c0 + 1]);
        accZ[ns][0] = sigmoidf_(accZ[ns][0] + bz0);
        accZ[ns][1] = sigmoidf_(accZ[ns][1] + bz1);
        accZ[ns][2] = sigmoidf_(accZ[ns][2] + bz0);
        accZ[ns][3] = sigmoidf_(accZ[ns][3] + bz1);

        float br0 = __ldg(&g_bias[D + c0]), br1 = __ldg(&g_bias[D + c0 + 1]);
        int r1 = mrow0 + g;
        int swc = c0 ^ (g << 2);
        float2 hA = *(float2*)(sm + HS + r1 * D + swc);
        float2 hB = *(float2*)(sm + HS + (r1 + 8) * D + swc);
        float q0 = sigmoidf_(accR[ns][0] + br0);
        float q1 = sigmoidf_(accR[ns][1] + br1);
        float q2 = sigmoidf_(accR[ns][2] + br0);
        float q3 = sigmoidf_(accR[ns][3] + br1);
        *(float2*)(sm + HS + r1 * D + swc)       = make_float2(f2tf(q0 * hA.x), f2tf(q1 * hA.y));
        *(float2*)(sm + HS + (r1 + 8) * D + swc) = make_float2(f2tf(q2 * hB.x), f2tf(q3 * hB.y));
        accR[ns][0] = 0.f; accR[ns][1] = 0.f; accR[ns][2] = 0.f; accR[ns][3] = 0.f;
    }
    // no extra sync needed: slabs 12-15 don't touch HS; syncs separate E1 from slab 16

    // hc_pre = x@Wh^T + rh@Uh^T   (accR reused as accH)
    QITER(12, XS, accR); QITER(13, XS, accR); QITER(14, XS, accR); QITER(15, XS, accR);
    QITER(16, HS, accR); QITER(17, HS, accR); QITER(18, HS, accR); QITER(19, HS, accR);
#undef QITER

    // ---- E2: h_cand = tanh(hc_pre+bh); h_t = (1-z)*h_exact + z*h_cand ----
#pragma unroll
    for (int ns = 0; ns < 4; ++ns) {
        int c0 = ncol0 + ns * 8 + 2 * t;
        float bh0 = __ldg(&g_bias[2 * D + c0]), bh1 = __ldg(&g_bias[2 * D + c0 + 1]);
        long long gr1 = row0 + mrow0 + g, gr2 = gr1 + 8;
        float2 hA = *(const float2*)(h + gr1 * D + c0);   // exact h from gmem
        float2 hB = *(const float2*)(h + gr2 * D + c0);
        float hc0 = tanhf(accR[ns][0] + bh0);
        float hc1 = tanhf(accR[ns][1] + bh1);
        float hc2 = tanhf(accR[ns][2] + bh0);
        float hc3 = tanhf(accR[ns][3] + bh1);
        float ht0 = (1.f - accZ[ns][0]) * hA.x + accZ[ns][0] * hc0;
        float ht1 = (1.f - accZ[ns][1]) * hA.y + accZ[ns][1] * hc1;
        float ht2 = (1.f - accZ[ns][2]) * hB.x + accZ[ns][2] * hc2;
        float ht3 = (1.f - accZ[ns][3]) * hB.y + accZ[ns][3] * hc3;
        *(float2*)(out + gr1 * D + c0)            = make_float2(ht0, ht1);
        *(float2*)(out + gr2 * D + c0)            = make_float2(ht2, ht3);
        *(float2*)(out + half_off + gr1 * D + c0) = make_float2(hc0, hc1);
        *(float2*)(out + half_off + gr2 * D + c0) = make_float2(hc2, hc3);
    }
}

// ---------------------------------------------------------------------------
// launch
// ---------------------------------------------------------------------------
extern "C" void kernel_launch(void* const* d_in, const int* in_sizes, int n_in,
                              void* d_out, int out_size) {
    const float* x  = (const float*)d_in[0];
    const float* h  = (const float*)d_in[1];
    const float* Wz = (const float*)d_in[2];
    const float* Uz = (const float*)d_in[3];
    const float* Bz = (const float*)d_in[4];
    const float* Wr = (const float*)d_in[5];
    const float* Ur = (const float*)d_in[6];
    const float* Br = (const float*)d_in[7];
    const float* Wh = (const float*)d_in[8];
    const float* Uh = (const float*)d_in[9];
    const float* Bh = (const float*)d_in[10];

    const int rows = in_sizes[0] / D;      // 262144
    const int grid = rows / 64;            // 4096

    cudaFuncSetAttribute(gru_kernel, cudaFuncAttributeMaxDynamicSharedMemorySize, SMEM_BYTES);

    bias_kernel<<<1, D>>>(Bz, Br, Bh);
    prep_kernel<<<160, NT>>>(Wz, Uz, Wr, Ur, Wh, Uh);

    long long half_off = (long long)out_size / 2;   // h_t first, h_cand second
    gru_kernel<<<grid, NT, SMEM_BYTES>>>(x, h, (float*)d_out, half_off);
}

// round 14
// speedup vs baseline: 1.2693x; 1.1208x over previous
#include <cuda_runtime.h>
#include <stdint.h>

#define D  128
#define NT 512

// SMEM float offsets
#define XS 0            // x tile [64][128] tf32-rounded, swizzled (32KB)
#define HS 8192         // h tile [64][128] tf32-rounded; later r*h  (32KB)
#define PB 16384        // 3 x quarter-panel buffers (3 x 16KB)
#define SMEM_BYTES ((16384 + 3 * 4096) * 4)   // 114,688 B -> 2 CTAs/SM (224KB/228KB)

// ---------------------------------------------------------------------------
// device globals: biases + prepped weight panel images
// ---------------------------------------------------------------------------
__device__ float g_bias[3 * D];
__device__ __align__(256) float g_wp[20 * 4096];  // 20 quarter-panels (Wz,Uz,Wr+Ur,Wh,Uh) x 4

__device__ __forceinline__ float f2tf(float f) {      // round fp32 -> tf32 grid
    uint32_t u;
    asm("cvt.rna.tf32.f32 %0, %1;" : "=r"(u) : "f"(f));
    return __uint_as_float(u);
}
__device__ __forceinline__ float sigmoidf_(float v) { return 1.0f / (1.0f + expf(-v)); }

__device__ __forceinline__ uint32_t smem_u32(const void* p) {
    uint32_t a;
    asm("{ .reg .u64 t; cvta.to.shared.u64 t, %1; cvt.u32.u64 %0, t; }" : "=r"(a) : "l"(p));
    return a;
}
__device__ __forceinline__ void cp16(uint32_t saddr, const void* gaddr) {
    asm volatile("cp.async.cg.shared.global [%0], [%1], 16;" :: "r"(saddr), "l"(gaddr));
}
#define CP_COMMIT() asm volatile("cp.async.commit_group;" ::: "memory")
#define CP_WAIT1()  asm volatile("cp.async.wait_group 1;" ::: "memory")
#define CP_WAIT0()  asm volatile("cp.async.wait_group 0;" ::: "memory")

// ---------------------------------------------------------------------------
// prep: bake weights into SMEM-image layout (blocks 0..159) + bias sums (160..162)
// panel p = G*4 + q (G: Wz,Uz,Wr+Ur,Wh,Uh); element B_G(n,k), k = q*32+k',
// stored at p*4096 + n*32 + (k' ^ ((n&7)<<2)). G0..2 transposed, G3..4 natural.
// ---------------------------------------------------------------------------
__global__ void prep_kernel(const float* __restrict__ Wz, const float* __restrict__ Uz,
                            const float* __restrict__ Wr, const float* __restrict__ Ur,
                            const float* __restrict__ Wh, const float* __restrict__ Uh,
                            const float* __restrict__ Bz, const float* __restrict__ Br,
                            const float* __restrict__ Bh) {
    if (blockIdx.x >= 160) {                 // bias: one block per matrix
        int m = blockIdx.x - 160;
        int j = threadIdx.x;
        if (j < D) {
            const float* B = (m == 0) ? Bz : (m == 1) ? Br : Bh;
            float s = 0.f;
            for (int i = 0; i < D; ++i) s += B[i * D + j];   // coalesced
            g_bias[m * D + j] = s;
        }
        return;
    }
    int idx = blockIdx.x * blockDim.x + threadIdx.x;   // 81920 weight elements
    int G   = idx >> 14;
    int rem = idx & 16383;
    int q   = rem >> 12;
    int r2  = rem & 4095;
    int n   = r2 >> 5;
    int kx  = r2 & 31;
    int k   = q * 32 + (kx ^ ((n & 7) << 2));
    float v;
    if      (G == 0) v = Wz[k * D + n];
    else if (G == 1) v = Uz[k * D + n];
    else if (G == 2) v = Wr[k * D + n] + Ur[k * D + n];
    else if (G == 3) v = Wh[n * D + k];
    else             v = Uh[n * D + k];
    g_wp[idx] = f2tf(v);
}

// ---------------------------------------------------------------------------
// mma helpers
// ---------------------------------------------------------------------------
__device__ __forceinline__ void mma8(float* d, const uint32_t* a, uint32_t b0, uint32_t b1) {
    asm volatile(
        "mma.sync.aligned.m16n8k8.row.col.f32.tf32.tf32.f32 "
        "{%0,%1,%2,%3}, {%4,%5,%6,%7}, {%8,%9}, {%0,%1,%2,%3};"
        : "+f"(d[0]), "+f"(d[1]), "+f"(d[2]), "+f"(d[3])
        : "r"(a[0]), "r"(a[1]), "r"(a[2]), "r"(a[3]), "r"(b0), "r"(b1));
}

// one quarter-K slab: warp tile 16M x 32N x 32K
__device__ __forceinline__ void mma_q(const float* __restrict__ As, int koff,
                                      const float* __restrict__ Ws,
                                      float acc[4][4],
                                      int mrow0, int ncol0, int g, int t) {
    const float* a0 = As + (mrow0 + g) * D + koff;
    const float* a1 = a0 + 8 * D;
#pragma unroll
    for (int kk = 0; kk < 4; ++kk) {
        const int off1 = (kk * 8 + t) ^ (g << 2);
        const int off2 = off1 ^ 4;
        uint32_t A[4];
        A[0] = __float_as_uint(a0[off1]);
        A[1] = __float_as_uint(a1[off1]);
        A[2] = __float_as_uint(a0[off2]);
        A[3] = __float_as_uint(a1[off2]);
#pragma unroll
        for (int ns = 0; ns < 4; ++ns) {
            const float* bp = Ws + (ncol0 + ns * 8 + g) * 32;
            mma8(acc[ns], A, __float_as_uint(bp[off1]), __float_as_uint(bp[off2]));
        }
    }
}

// ---------------------------------------------------------------------------
// fused GRU: 64 rows/CTA, 512 threads (16 warps of 16x32), 2 CTAs/SM
// 20 quarter-slabs; cp.async triple-buffered panels; 1 sync per slab
// ---------------------------------------------------------------------------
__global__ __launch_bounds__(NT, 2)
void gru_kernel(const float* __restrict__ x, const float* __restrict__ h,
                float* __restrict__ out, long long half_off) {
    extern __shared__ float sm[];
    const int tid   = threadIdx.x;
    const int lane  = tid & 31;
    const int warp  = tid >> 5;
    const int g     = lane >> 2;
    const int t     = lane & 3;
    const int mrow0 = (warp >> 2) * 16;    // 0,16,32,48
    const int ncol0 = (warp & 3) * 32;     // 0,32,64,96
    const long long row0 = (long long)blockIdx.x * 64;

    const uint32_t pb = smem_u32(sm + PB) + (uint32_t)tid * 16;

    // ---- kick off panel pipeline: img0 -> buf0, img1 -> buf1 ----
    {
        const char* s0 = (const char*)g_wp + tid * 16;
        cp16(pb,          s0);
        cp16(pb + 8192,   s0 + 8192);
        CP_COMMIT();
        const char* s1 = (const char*)(g_wp + 4096) + tid * 16;
        cp16(pb + 16384,        s1);
        cp16(pb + 16384 + 8192, s1 + 8192);
        CP_COMMIT();
    }

    // ---- stage x, h (tf32-rounded) into swizzled tiles (overlaps cp.async) ----
#pragma unroll
    for (int i = 0; i < 4; ++i) {
        int idx = tid + i * NT;
        int r = idx >> 5, c = (idx & 31) << 2;
        int sw = r * D + (c ^ ((r & 7) << 2));
        float4 vx = *(const float4*)(x + (row0 + r) * D + c);
        *(float4*)(sm + XS + sw) = make_float4(f2tf(vx.x), f2tf(vx.y), f2tf(vx.z), f2tf(vx.w));
        float4 vh = *(const float4*)(h + (row0 + r) * D + c);
        *(float4*)(sm + HS + sw) = make_float4(f2tf(vh.x), f2tf(vh.y), f2tf(vh.z), f2tf(vh.w));
    }
    CP_WAIT1();             // img0 complete
    __syncthreads();

    float accZ[4][4], accR[4][4];
#pragma unroll
    for (int ns = 0; ns < 4; ++ns)
#pragma unroll
        for (int j = 0; j < 4; ++j) { accZ[ns][j] = 0.f; accR[ns][j] = 0.f; }

    // slab p: issue img p+2 -> buf (p+2)%3; mma img p; wait img p+1; sync
#define QITER(p, ABASE, ACC) do {                                              \
        if ((p) + 2 <= 19) {                                                   \
            uint32_t dst = pb + (uint32_t)((((p) + 2) % 3) * 16384);           \
            const char* s_ = (const char*)(g_wp + ((p) + 2) * 4096) + tid * 16;\
            cp16(dst, s_); cp16(dst + 8192, s_ + 8192);                        \
            CP_COMMIT();                                                       \
        }                                                                      \
        mma_q(sm + (ABASE), ((p) & 3) * 32, sm + PB + (((p) % 3) * 4096),      \
              ACC, mrow0, ncol0, g, t);                                        \
        if ((p) + 2 <= 19) { CP_WAIT1(); } else { CP_WAIT0(); }                \
        __syncthreads();                                                       \
    } while (0)

    // z_pre = x@Wz + h@Uz
    QITER(0, XS, accZ);  QITER(1, XS, accZ);  QITER(2, XS, accZ);  QITER(3, XS, accZ);
    QITER(4, HS, accZ);  QITER(5, HS, accZ);  QITER(6, HS, accZ);  QITER(7, HS, accZ);
    // r_pre = x@(Wr+Ur)
    QITER(8, XS, accR);  QITER(9, XS, accR);  QITER(10, XS, accR); QITER(11, XS, accR);

    // ---- E1: z = sigmoid(z_pre+bz) in accZ; HS <- f2tf(sigmoid(r_pre+br) * h) ----
#pragma unroll
    for (int ns = 0; ns < 4; ++ns) {
        int c0 = ncol0 + ns * 8 + 2 * t;
        float bz0 = __ldg(&g_bias[c0]), bz1 = __ldg(&g_bias[c0 + 1]);
        accZ[ns][0] = sigmoidf_(accZ[ns][0] + bz0);
        accZ[ns][1] = sigmoidf_(accZ[ns][1] + bz1);
        accZ[ns][2] = sigmoidf_(accZ[ns][2] + bz0);
        accZ[ns][3] = sigmoidf_(accZ[ns][3] + bz1);

        float br0 = __ldg(&g_bias[D + c0]), br1 = __ldg(&g_bias[D + c0 + 1]);
        int r1 = mrow0 + g;
        int swc = c0 ^ (g << 2);
        float2 hA = *(float2*)(sm + HS + r1 * D + swc);
        float2 hB = *(float2*)(sm + HS + (r1 + 8) * D + swc);
        float q0 = sigmoidf_(accR[ns][0] + br0);
        float q1 = sigmoidf_(accR[ns][1] + br1);
        float q2 = sigmoidf_(accR[ns][2] + br0);
        float q3 = sigmoidf_(accR[ns][3] + br1);
        *(float2*)(sm + HS + r1 * D + swc)       = make_float2(f2tf(q0 * hA.x), f2tf(q1 * hA.y));
        *(float2*)(sm + HS + (r1 + 8) * D + swc) = make_float2(f2tf(q2 * hB.x), f2tf(q3 * hB.y));
        accR[ns][0] = 0.f; accR[ns][1] = 0.f; accR[ns][2] = 0.f; accR[ns][3] = 0.f;
    }
    // slabs 12-15 read XS only; syncs separate the HS writes from slab 16

    // hc_pre = x@Wh^T + rh@Uh^T   (accR reused)
    QITER(12, XS, accR); QITER(13, XS, accR); QITER(14, XS, accR); QITER(15, XS, accR);
    QITER(16, HS, accR); QITER(17, HS, accR); QITER(18, HS, accR); QITER(19, HS, accR);
#undef QITER

    // ---- E2: h_cand = tanh(hc_pre+bh); h_t = (1-z)*h_exact + z*h_cand ----
#pragma unroll
    for (int ns = 0; ns < 4; ++ns) {
        int c0 = ncol0 + ns * 8 + 2 * t;
        float bh0 = __ldg(&g_bias[2 * D + c0]), bh1 = __ldg(&g_bias[2 * D + c0 + 1]);
        long long gr1 = row0 + mrow0 + g, gr2 = gr1 + 8;
        float2 hA = *(const float2*)(h + gr1 * D + c0);   // exact h from gmem
        float2 hB = *(const float2*)(h + gr2 * D + c0);
        float hc0 = tanhf(accR[ns][0] + bh0);
        float hc1 = tanhf(accR[ns][1] + bh1);
        float hc2 = tanhf(accR[ns][2] + bh0);
        float hc3 = tanhf(accR[ns][3] + bh1);
        float ht0 = (1.f - accZ[ns][0]) * hA.x + accZ[ns][0] * hc0;
        float ht1 = (1.f - accZ[ns][1]) * hA.y + accZ[ns][1] * hc1;
        float ht2 = (1.f - accZ[ns][2]) * hB.x + accZ[ns][2] * hc2;
        float ht3 = (1.f - accZ[ns][3]) * hB.y + accZ[ns][3] * hc3;
        *(float2*)(out + gr1 * D + c0)            = make_float2(ht0, ht1);
        *(float2*)(out + gr2 * D + c0)            = make_float2(ht2, ht3);
        *(float2*)(out + half_off + gr1 * D + c0) = make_float2(hc0, hc1);
        *(float2*)(out + half_off + gr2 * D + c0) = make_float2(hc2, hc3);
    }
}

// ---------------------------------------------------------------------------
// launch: exactly 2 kernels per call (prep+bias fused, then gru)
// ---------------------------------------------------------------------------
extern "C" void kernel_launch(void* const* d_in, const int* in_sizes, int n_in,
                              void* d_out, int out_size) {
    const float* x  = (const float*)d_in[0];
    const float* h  = (const float*)d_in[1];
    const float* Wz = (const float*)d_in[2];
    const float* Uz = (const float*)d_in[3];
    const float* Bz = (const float*)d_in[4];
    const float* Wr = (const float*)d_in[5];
    const float* Ur = (const float*)d_in[6];
    const float* Br = (const float*)d_in[7];
    const float* Wh = (const float*)d_in[8];
    const float* Uh = (const float*)d_in[9];
    const float* Bh = (const float*)d_in[10];

    const int rows = in_sizes[0] / D;      // 262144
    const int grid = rows / 64;            // 4096

    cudaFuncSetAttribute(gru_kernel, cudaFuncAttributeMaxDynamicSharedMemorySize, SMEM_BYTES);

    prep_kernel<<<163, NT>>>(Wz, Uz, Wr, Ur, Wh, Uh, Bz, Br, Bh);

    long long half_off = (long long)out_size / 2;   // h_t first, h_cand second
    gru_kernel<<<grid, NT, SMEM_BYTES>>>(x, h, (float*)d_out, half_off);
}